// round 1
// baseline (speedup 1.0000x reference)
#include <cuda_runtime.h>
#include <math.h>

#define NODES 50000
#define EDGES 800000
// D_IN = D_H = 256, D_OUT = 128 (hardcoded below)

// ---------------- scratch (static device globals; no allocs allowed) ----------
__device__ float g_agg1[NODES * 256];   // segment_sum(x[src]) by dst
__device__ float g_h   [NODES * 256];   // relu(mean1@W1l + b1 + x@W1r)
__device__ float g_p   [NODES * 256];   // cols [0,128): h@W2l ; cols [128,256): h@W2r
__device__ float g_agg2[NODES * 128];   // segment_sum((h@W2l)[src]) by dst
__device__ int   g_cnt [NODES];
__device__ float g_inv [NODES];
__device__ int   g_src [EDGES];
__device__ int   g_dst [EDGES];

// ---------------- init: zero the accumulators ---------------------------------
__global__ void k_init() {
    int i = blockIdx.x * blockDim.x + threadIdx.x;
    if (i < NODES * 256) g_agg1[i] = 0.f;
    if (i < NODES * 128) g_agg2[i] = 0.f;
    if (i < NODES)       g_cnt[i]  = 0;
}

// ---------------- edge decode (int64 vs int32 robust) + degree count ----------
__global__ void k_edges(const void* __restrict__ ei_raw) {
    int e = blockIdx.x * blockDim.x + threadIdx.x;
    if (e >= EDGES) return;
    const int* w = (const int*)ei_raw;
    // int64 little-endian: high 4-byte words of nonneg values < 2^31 are all 0.
    // int32: those words are random node indices; P(all 8 zero) ~ (2e-5)^8 ~ 0.
    bool is64 = ((w[1] | w[3] | w[5] | w[7] | w[9] | w[11] | w[13] | w[15]) == 0);
    int s, d;
    if (is64) {
        const long long* e64 = (const long long*)ei_raw;
        s = (int)e64[e];
        d = (int)e64[EDGES + e];
    } else {
        s = w[e];
        d = w[EDGES + e];
    }
    g_src[e] = s;
    g_dst[e] = d;
    atomicAdd(&g_cnt[d], 1);
}

__global__ void k_inv() {
    int i = blockIdx.x * blockDim.x + threadIdx.x;
    if (i < NODES) g_inv[i] = 1.f / fmaxf((float)g_cnt[i], 1.f);
}

// ---------------- layer-1 scatter: agg1[dst] += x[src]  (warp per edge) -------
__global__ void k_scatter1(const float* __restrict__ x) {
    int gw   = (blockIdx.x * blockDim.x + threadIdx.x) >> 5;
    int lane = threadIdx.x & 31;
    if (gw >= EDGES) return;
    int src = g_src[gw];
    int dst = g_dst[gw];
    const float4* xr = (const float4*)(x + (size_t)src * 256);
    float* ar = g_agg1 + (size_t)dst * 256;
#pragma unroll
    for (int i = 0; i < 2; i++) {
        float4 v = xr[lane + 32 * i];
        int b = (lane + 32 * i) * 4;
        atomicAdd(ar + b + 0, v.x);
        atomicAdd(ar + b + 1, v.y);
        atomicAdd(ar + b + 2, v.z);
        atomicAdd(ar + b + 3, v.w);
    }
}

// ---------------- GEMM 1: h = relu((agg1*inv)@W1l + x@W1r + b1) ----------------
// BM=BN=128, BK=8, 256 threads, 8x8 per thread. Two K-passes share accumulators.
__global__ void k_gemm1(const float* __restrict__ x,
                        const float* __restrict__ W1l,
                        const float* __restrict__ b1,
                        const float* __restrict__ W1r) {
    __shared__ float As[8][132];
    __shared__ float Bs[8][128];
    const int t  = threadIdx.x;
    const int tx = t & 15, ty = t >> 4;
    const int row0 = blockIdx.y * 128, col0 = blockIdx.x * 128;

    float acc[8][8];
#pragma unroll
    for (int i = 0; i < 8; i++)
#pragma unroll
        for (int j = 0; j < 8; j++) acc[i][j] = 0.f;

    const int lr = t >> 1;           // A-load row within tile (0..127)
    const int lk = (t & 1) * 4;      // A-load k offset (0 or 4)
    const int br = t >> 5;           // B-load k row (0..7)
    const int bc = (t & 31) * 4;     // B-load col (0..124)

#pragma unroll 1
    for (int pass = 0; pass < 2; pass++) {
        const float* A = pass ? x    : g_agg1;
        const float* B = pass ? W1r  : W1l;
#pragma unroll 1
        for (int kk = 0; kk < 256; kk += 8) {
            int gr = row0 + lr;
            float4 av = make_float4(0.f, 0.f, 0.f, 0.f);
            if (gr < NODES) {
                av = *(const float4*)(A + (size_t)gr * 256 + kk + lk);
                if (pass == 0) {
                    float s = g_inv[gr];
                    av.x *= s; av.y *= s; av.z *= s; av.w *= s;
                }
            }
            As[lk + 0][lr] = av.x;
            As[lk + 1][lr] = av.y;
            As[lk + 2][lr] = av.z;
            As[lk + 3][lr] = av.w;
            float4 bv = *(const float4*)(B + (size_t)(kk + br) * 256 + col0 + bc);
            *(float4*)&Bs[br][bc] = bv;
            __syncthreads();
#pragma unroll
            for (int k = 0; k < 8; k++) {
                float a[8], b[8];
                *(float4*)&a[0] = *(const float4*)&As[k][ty * 8];
                *(float4*)&a[4] = *(const float4*)&As[k][ty * 8 + 4];
                *(float4*)&b[0] = *(const float4*)&Bs[k][tx * 8];
                *(float4*)&b[4] = *(const float4*)&Bs[k][tx * 8 + 4];
#pragma unroll
                for (int i = 0; i < 8; i++)
#pragma unroll
                    for (int j = 0; j < 8; j++) acc[i][j] += a[i] * b[j];
            }
            __syncthreads();
        }
    }

#pragma unroll
    for (int i = 0; i < 8; i++) {
        int r = row0 + ty * 8 + i;
        if (r < NODES) {
#pragma unroll
            for (int j = 0; j < 8; j++) {
                int c = col0 + tx * 8 + j;
                g_h[(size_t)r * 256 + c] = fmaxf(acc[i][j] + b1[c], 0.f);
            }
        }
    }
}

// ---------------- GEMM 2: p = h@[W2l | W2r]  (block col chooses the matrix) ---
__global__ void k_gemm2(const float* __restrict__ W2l,
                        const float* __restrict__ W2r) {
    __shared__ float As[8][132];
    __shared__ float Bs[8][128];
    const int t  = threadIdx.x;
    const int tx = t & 15, ty = t >> 4;
    const int row0 = blockIdx.y * 128;
    const int col0 = blockIdx.x * 128;
    const float* B = blockIdx.x ? W2r : W2l;   // each B is [256,128] row-major

    float acc[8][8];
#pragma unroll
    for (int i = 0; i < 8; i++)
#pragma unroll
        for (int j = 0; j < 8; j++) acc[i][j] = 0.f;

    const int lr = t >> 1;
    const int lk = (t & 1) * 4;
    const int br = t >> 5;
    const int bc = (t & 31) * 4;

#pragma unroll 1
    for (int kk = 0; kk < 256; kk += 8) {
        int gr = row0 + lr;
        float4 av = (gr < NODES)
                        ? *(const float4*)(g_h + (size_t)gr * 256 + kk + lk)
                        : make_float4(0.f, 0.f, 0.f, 0.f);
        As[lk + 0][lr] = av.x;
        As[lk + 1][lr] = av.y;
        As[lk + 2][lr] = av.z;
        As[lk + 3][lr] = av.w;
        float4 bv = *(const float4*)(B + (size_t)(kk + br) * 128 + bc);
        *(float4*)&Bs[br][bc] = bv;
        __syncthreads();
#pragma unroll
        for (int k = 0; k < 8; k++) {
            float a[8], b[8];
            *(float4*)&a[0] = *(const float4*)&As[k][ty * 8];
            *(float4*)&a[4] = *(const float4*)&As[k][ty * 8 + 4];
            *(float4*)&b[0] = *(const float4*)&Bs[k][tx * 8];
            *(float4*)&b[4] = *(const float4*)&Bs[k][tx * 8 + 4];
#pragma unroll
            for (int i = 0; i < 8; i++)
#pragma unroll
                for (int j = 0; j < 8; j++) acc[i][j] += a[i] * b[j];
        }
        __syncthreads();
    }

#pragma unroll
    for (int i = 0; i < 8; i++) {
        int r = row0 + ty * 8 + i;
        if (r < NODES) {
#pragma unroll
            for (int j = 0; j < 8; j++) {
                g_p[(size_t)r * 256 + col0 + tx * 8 + j] = acc[i][j];
            }
        }
    }
}

// ---------------- layer-2 scatter: agg2[dst] += p[src, 0:128] ------------------
__global__ void k_scatter2() {
    int gw   = (blockIdx.x * blockDim.x + threadIdx.x) >> 5;
    int lane = threadIdx.x & 31;
    if (gw >= EDGES) return;
    int src = g_src[gw];
    int dst = g_dst[gw];
    float4 v = *((const float4*)(g_p + (size_t)src * 256) + lane);  // cols 0..127
    float* a = g_agg2 + (size_t)dst * 128 + lane * 4;
    atomicAdd(a + 0, v.x);
    atomicAdd(a + 1, v.y);
    atomicAdd(a + 2, v.z);
    atomicAdd(a + 3, v.w);
}

// ---------------- final: out = sigmoid(agg2*inv + b2 + r) ----------------------
__global__ void k_final(const float* __restrict__ b2, float* __restrict__ out) {
    int i = blockIdx.x * blockDim.x + threadIdx.x;
    if (i >= NODES * 128) return;
    int n = i >> 7, j = i & 127;
    float v = g_agg2[i] * g_inv[n] + b2[j] + g_p[(size_t)n * 256 + 128 + j];
    out[i] = 1.f / (1.f + expf(-v));
}

// ---------------- launch -------------------------------------------------------
extern "C" void kernel_launch(void* const* d_in, const int* in_sizes, int n_in,
                              void* d_out, int out_size) {
    (void)in_sizes; (void)n_in; (void)out_size;
    const float* x   = (const float*)d_in[0];
    const void*  ei  = d_in[1];                 // int64 or int32; decoded on device
    const float* W1l = (const float*)d_in[2];
    const float* b1  = (const float*)d_in[3];
    const float* W1r = (const float*)d_in[4];
    const float* W2l = (const float*)d_in[5];
    const float* b2  = (const float*)d_in[6];
    const float* W2r = (const float*)d_in[7];
    float* out = (float*)d_out;

    k_init<<<(NODES * 256 + 255) / 256, 256>>>();
    k_edges<<<(EDGES + 255) / 256, 256>>>(ei);
    k_inv<<<(NODES + 255) / 256, 256>>>();
    k_scatter1<<<(EDGES * 32 + 255) / 256, 256>>>(x);
    dim3 grid_g(2, (NODES + 127) / 128);
    k_gemm1<<<grid_g, 256>>>(x, W1l, b1, W1r);
    k_gemm2<<<grid_g, 256>>>(W2l, W2r);
    k_scatter2<<<(EDGES * 32 + 255) / 256, 256>>>();
    k_final<<<(NODES * 128 + 255) / 256, 256>>>(b2, out);
}

// round 2
// speedup vs baseline: 1.8166x; 1.8166x over previous
#include <cuda_runtime.h>
#include <math.h>

#define NODES 50000
#define EDGES 800000
// D_IN = D_H = 256, D_OUT = 128 (hardcoded below)

// ---------------- scratch (static device globals; no allocs allowed) ----------
__device__ float g_agg1[NODES * 256];   // mean of x[src] by dst
__device__ float g_h   [NODES * 256];   // relu(mean1@W1l + b1 + x@W1r)
__device__ float g_p   [NODES * 256];   // cols [0,128): h@W2l ; cols [128,256): h@W2r
__device__ int   g_cnt [NODES];
__device__ float g_inv [NODES];
__device__ int   g_src [EDGES];
__device__ int   g_dst [EDGES];
__device__ int   g_off [NODES + 1];     // CSR row offsets (by dst)
__device__ int   g_cur [NODES];         // bucket cursors
__device__ int   g_esrc[EDGES];         // src ids grouped by dst

// ---------------- init: zero the small counters --------------------------------
__global__ void k_init() {
    int i = blockIdx.x * blockDim.x + threadIdx.x;
    if (i < NODES) { g_cnt[i] = 0; g_cur[i] = 0; }
}

// ---------------- edge decode (int64 vs int32 robust) + degree count ----------
__global__ void k_edges(const void* __restrict__ ei_raw) {
    int e = blockIdx.x * blockDim.x + threadIdx.x;
    if (e >= EDGES) return;
    const int* w = (const int*)ei_raw;
    // int64 little-endian: high words of nonneg values < 2^31 are all zero.
    bool is64 = ((w[1] | w[3] | w[5] | w[7] | w[9] | w[11] | w[13] | w[15]) == 0);
    int s, d;
    if (is64) {
        const long long* e64 = (const long long*)ei_raw;
        s = (int)e64[e];
        d = (int)e64[EDGES + e];
    } else {
        s = w[e];
        d = w[EDGES + e];
    }
    g_src[e] = s;
    g_dst[e] = d;
    atomicAdd(&g_cnt[d], 1);
}

__global__ void k_inv() {
    int i = blockIdx.x * blockDim.x + threadIdx.x;
    if (i < NODES) g_inv[i] = 1.f / fmaxf((float)g_cnt[i], 1.f);
}

// ---------------- exclusive scan of degrees -> CSR offsets (1 block) ----------
__global__ void k_scan() {
    __shared__ int sums[1024];
    const int C = (NODES + 1023) / 1024;      // 49
    int t = threadIdx.x;
    int beg = t * C;
    int end = min(beg + C, NODES);
    int s = 0;
    for (int i = beg; i < end; i++) s += g_cnt[i];
    sums[t] = s;
    __syncthreads();
    for (int d = 1; d < 1024; d <<= 1) {
        int add = (t >= d) ? sums[t - d] : 0;
        __syncthreads();
        sums[t] += add;
        __syncthreads();
    }
    int run = sums[t] - s;                    // exclusive prefix
    for (int i = beg; i < end; i++) { g_off[i] = run; run += g_cnt[i]; }
    if (t == 1023) g_off[NODES] = EDGES;
}

// ---------------- bucket fill: group src ids by dst ---------------------------
__global__ void k_fill() {
    int e = blockIdx.x * blockDim.x + threadIdx.x;
    if (e >= EDGES) return;
    int d = g_dst[e];
    int p = atomicAdd(&g_cur[d], 1);
    g_esrc[g_off[d] + p] = g_src[e];
}

// ---------------- layer-1 gather: agg1[n] = mean over nbrs of x ---------------
// Two warps per node (128 cols each); lane owns one float4.
__global__ void k_gather1(const float* __restrict__ x) {
    int gw   = (blockIdx.x * blockDim.x + threadIdx.x) >> 5;
    int node = gw >> 1;
    if (node >= NODES) return;
    int half = gw & 1;
    int lane = threadIdx.x & 31;
    int c = half * 128 + lane * 4;

    int e   = g_off[node];
    int end = g_off[node + 1];
    float4 acc = make_float4(0.f, 0.f, 0.f, 0.f);
    for (; e + 1 < end; e += 2) {
        int s0 = g_esrc[e], s1 = g_esrc[e + 1];
        float4 v0 = *(const float4*)(x + (size_t)s0 * 256 + c);
        float4 v1 = *(const float4*)(x + (size_t)s1 * 256 + c);
        acc.x += v0.x; acc.y += v0.y; acc.z += v0.z; acc.w += v0.w;
        acc.x += v1.x; acc.y += v1.y; acc.z += v1.z; acc.w += v1.w;
    }
    if (e < end) {
        int s0 = g_esrc[e];
        float4 v0 = *(const float4*)(x + (size_t)s0 * 256 + c);
        acc.x += v0.x; acc.y += v0.y; acc.z += v0.z; acc.w += v0.w;
    }
    float inv = g_inv[node];
    acc.x *= inv; acc.y *= inv; acc.z *= inv; acc.w *= inv;
    *(float4*)(g_agg1 + (size_t)node * 256 + c) = acc;
}

// ---------------- GEMM 1: h = relu(agg1@W1l + x@W1r + b1) ----------------------
// BM=BN=128, BK=8, 256 threads, 8x8 per thread. Two K-passes share accumulators.
__global__ void k_gemm1(const float* __restrict__ x,
                        const float* __restrict__ W1l,
                        const float* __restrict__ b1,
                        const float* __restrict__ W1r) {
    __shared__ float As[8][132];
    __shared__ float Bs[8][128];
    const int t  = threadIdx.x;
    const int tx = t & 15, ty = t >> 4;
    const int row0 = blockIdx.y * 128, col0 = blockIdx.x * 128;

    float acc[8][8];
#pragma unroll
    for (int i = 0; i < 8; i++)
#pragma unroll
        for (int j = 0; j < 8; j++) acc[i][j] = 0.f;

    const int lr = t >> 1;           // A-load row within tile (0..127)
    const int lk = (t & 1) * 4;      // A-load k offset (0 or 4)
    const int br = t >> 5;           // B-load k row (0..7)
    const int bc = (t & 31) * 4;     // B-load col (0..124)

#pragma unroll 1
    for (int pass = 0; pass < 2; pass++) {
        const float* A = pass ? x   : g_agg1;
        const float* B = pass ? W1r : W1l;
#pragma unroll 1
        for (int kk = 0; kk < 256; kk += 8) {
            int gr = row0 + lr;
            float4 av = make_float4(0.f, 0.f, 0.f, 0.f);
            if (gr < NODES) av = *(const float4*)(A + (size_t)gr * 256 + kk + lk);
            As[lk + 0][lr] = av.x;
            As[lk + 1][lr] = av.y;
            As[lk + 2][lr] = av.z;
            As[lk + 3][lr] = av.w;
            float4 bv = *(const float4*)(B + (size_t)(kk + br) * 256 + col0 + bc);
            *(float4*)&Bs[br][bc] = bv;
            __syncthreads();
#pragma unroll
            for (int k = 0; k < 8; k++) {
                float a[8], b[8];
                *(float4*)&a[0] = *(const float4*)&As[k][ty * 8];
                *(float4*)&a[4] = *(const float4*)&As[k][ty * 8 + 4];
                *(float4*)&b[0] = *(const float4*)&Bs[k][tx * 8];
                *(float4*)&b[4] = *(const float4*)&Bs[k][tx * 8 + 4];
#pragma unroll
                for (int i = 0; i < 8; i++)
#pragma unroll
                    for (int j = 0; j < 8; j++) acc[i][j] += a[i] * b[j];
            }
            __syncthreads();
        }
    }

#pragma unroll
    for (int i = 0; i < 8; i++) {
        int r = row0 + ty * 8 + i;
        if (r < NODES) {
#pragma unroll
            for (int j = 0; j < 8; j++) {
                int c = col0 + tx * 8 + j;
                g_h[(size_t)r * 256 + c] = fmaxf(acc[i][j] + b1[c], 0.f);
            }
        }
    }
}

// ---------------- GEMM 2: p = h@[W2l | W2r]  (block col chooses the matrix) ---
__global__ void k_gemm2(const float* __restrict__ W2l,
                        const float* __restrict__ W2r) {
    __shared__ float As[8][132];
    __shared__ float Bs[8][128];
    const int t  = threadIdx.x;
    const int tx = t & 15, ty = t >> 4;
    const int row0 = blockIdx.y * 128;
    const int col0 = blockIdx.x * 128;
    const float* B = blockIdx.x ? W2r : W2l;   // each B is [256,128] row-major

    float acc[8][8];
#pragma unroll
    for (int i = 0; i < 8; i++)
#pragma unroll
        for (int j = 0; j < 8; j++) acc[i][j] = 0.f;

    const int lr = t >> 1;
    const int lk = (t & 1) * 4;
    const int br = t >> 5;
    const int bc = (t & 31) * 4;

#pragma unroll 1
    for (int kk = 0; kk < 256; kk += 8) {
        int gr = row0 + lr;
        float4 av = (gr < NODES)
                        ? *(const float4*)(g_h + (size_t)gr * 256 + kk + lk)
                        : make_float4(0.f, 0.f, 0.f, 0.f);
        As[lk + 0][lr] = av.x;
        As[lk + 1][lr] = av.y;
        As[lk + 2][lr] = av.z;
        As[lk + 3][lr] = av.w;
        float4 bv = *(const float4*)(B + (size_t)(kk + br) * 128 + bc);
        *(float4*)&Bs[br][bc] = bv;
        __syncthreads();
#pragma unroll
        for (int k = 0; k < 8; k++) {
            float a[8], b[8];
            *(float4*)&a[0] = *(const float4*)&As[k][ty * 8];
            *(float4*)&a[4] = *(const float4*)&As[k][ty * 8 + 4];
            *(float4*)&b[0] = *(const float4*)&Bs[k][tx * 8];
            *(float4*)&b[4] = *(const float4*)&Bs[k][tx * 8 + 4];
#pragma unroll
            for (int i = 0; i < 8; i++)
#pragma unroll
                for (int j = 0; j < 8; j++) acc[i][j] += a[i] * b[j];
        }
        __syncthreads();
    }

#pragma unroll
    for (int i = 0; i < 8; i++) {
        int r = row0 + ty * 8 + i;
        if (r < NODES) {
#pragma unroll
            for (int j = 0; j < 8; j++) {
                g_p[(size_t)r * 256 + col0 + tx * 8 + j] = acc[i][j];
            }
        }
    }
}

// ---- layer-2 gather fused with epilogue: out = sigmoid(mean(p_l)+b2+p_r) -----
// One warp per node; lane owns one float4 of the 128 output cols.
__global__ void k_gather2_final(const float* __restrict__ b2,
                                float* __restrict__ out) {
    int node = (blockIdx.x * blockDim.x + threadIdx.x) >> 5;
    if (node >= NODES) return;
    int lane = threadIdx.x & 31;
    int c = lane * 4;

    int e   = g_off[node];
    int end = g_off[node + 1];
    float4 acc = make_float4(0.f, 0.f, 0.f, 0.f);
    for (; e + 1 < end; e += 2) {
        int s0 = g_esrc[e], s1 = g_esrc[e + 1];
        float4 v0 = *(const float4*)(g_p + (size_t)s0 * 256 + c);
        float4 v1 = *(const float4*)(g_p + (size_t)s1 * 256 + c);
        acc.x += v0.x; acc.y += v0.y; acc.z += v0.z; acc.w += v0.w;
        acc.x += v1.x; acc.y += v1.y; acc.z += v1.z; acc.w += v1.w;
    }
    if (e < end) {
        int s0 = g_esrc[e];
        float4 v0 = *(const float4*)(g_p + (size_t)s0 * 256 + c);
        acc.x += v0.x; acc.y += v0.y; acc.z += v0.z; acc.w += v0.w;
    }
    float inv = g_inv[node];
    float4 bb = *(const float4*)(b2 + c);
    float4 rr = *(const float4*)(g_p + (size_t)node * 256 + 128 + c);
    float4 o;
    o.x = 1.f / (1.f + expf(-(acc.x * inv + bb.x + rr.x)));
    o.y = 1.f / (1.f + expf(-(acc.y * inv + bb.y + rr.y)));
    o.z = 1.f / (1.f + expf(-(acc.z * inv + bb.z + rr.z)));
    o.w = 1.f / (1.f + expf(-(acc.w * inv + bb.w + rr.w)));
    *(float4*)(out + (size_t)node * 128 + c) = o;
}

// ---------------- launch -------------------------------------------------------
extern "C" void kernel_launch(void* const* d_in, const int* in_sizes, int n_in,
                              void* d_out, int out_size) {
    (void)in_sizes; (void)n_in; (void)out_size;
    const float* x   = (const float*)d_in[0];
    const void*  ei  = d_in[1];                 // int64 or int32; decoded on device
    const float* W1l = (const float*)d_in[2];
    const float* b1  = (const float*)d_in[3];
    const float* W1r = (const float*)d_in[4];
    const float* W2l = (const float*)d_in[5];
    const float* b2  = (const float*)d_in[6];
    const float* W2r = (const float*)d_in[7];
    float* out = (float*)d_out;

    k_init<<<(NODES + 255) / 256, 256>>>();
    k_edges<<<(EDGES + 255) / 256, 256>>>(ei);
    k_inv<<<(NODES + 255) / 256, 256>>>();
    k_scan<<<1, 1024>>>();
    k_fill<<<(EDGES + 255) / 256, 256>>>();
    k_gather1<<<(NODES * 2 * 32 + 255) / 256, 256>>>(x);
    dim3 grid_g(2, (NODES + 127) / 128);
    k_gemm1<<<grid_g, 256>>>(x, W1l, b1, W1r);
    k_gemm2<<<grid_g, 256>>>(W2l, W2r);
    k_gather2_final<<<(NODES * 32 + 255) / 256, 256>>>(b2, out);
}

// round 3
// speedup vs baseline: 1.9822x; 1.0912x over previous
#include <cuda_runtime.h>
#include <math.h>

#define NODES 50000
#define EDGES 800000
// D_IN = D_H = 256, D_OUT = 128 (hardcoded below)

// ---------------- scratch (static device globals; no allocs allowed) ----------
__device__ float g_agg1[NODES * 256];   // mean of x[src] by dst
__device__ float g_h   [NODES * 256];   // relu(mean1@W1l + b1 + x@W1r)
__device__ float g_p   [NODES * 256];   // cols [0,128): h@W2l ; cols [128,256): h@W2r
__device__ int   g_cnt [NODES];
__device__ float g_inv [NODES];
__device__ int   g_src [EDGES];
__device__ int   g_dst [EDGES];
__device__ int   g_off [NODES];         // bucket start (order-free allocation)
__device__ int   g_cur [NODES];         // bucket cursors
__device__ int   g_esrc[EDGES];         // src ids grouped by dst
__device__ int   g_total;               // global bucket cursor

// ---------------- init: zero the small counters --------------------------------
__global__ void k_init() {
    int i = blockIdx.x * blockDim.x + threadIdx.x;
    if (i < NODES) { g_cnt[i] = 0; g_cur[i] = 0; }
    if (i == 0) g_total = 0;
}

// ---------------- edge decode (int64 vs int32 robust) + degree count ----------
__global__ void k_edges(const void* __restrict__ ei_raw) {
    int e = blockIdx.x * blockDim.x + threadIdx.x;
    if (e >= EDGES) return;
    const int* w = (const int*)ei_raw;
    // int64 little-endian: high words of nonneg values < 2^31 are all zero.
    bool is64 = ((w[1] | w[3] | w[5] | w[7] | w[9] | w[11] | w[13] | w[15]) == 0);
    int s, d;
    if (is64) {
        const long long* e64 = (const long long*)ei_raw;
        s = (int)e64[e];
        d = (int)e64[EDGES + e];
    } else {
        s = w[e];
        d = w[EDGES + e];
    }
    g_src[e] = s;
    g_dst[e] = d;
    atomicAdd(&g_cnt[d], 1);
}

// ------- bucket allocation: per-block scan + one global atomic; also 1/deg ----
__global__ void k_alloc() {
    __shared__ int s[256];
    __shared__ int base;
    int t = threadIdx.x;
    int i = blockIdx.x * 256 + t;
    int v = (i < NODES) ? g_cnt[i] : 0;
    s[t] = v;
    __syncthreads();
#pragma unroll
    for (int d = 1; d < 256; d <<= 1) {
        int add = (t >= d) ? s[t - d] : 0;
        __syncthreads();
        s[t] += add;
        __syncthreads();
    }
    int incl = s[t];
    if (t == 255) base = atomicAdd(&g_total, incl);
    __syncthreads();
    if (i < NODES) {
        g_off[i] = base + incl - v;
        g_inv[i] = 1.f / fmaxf((float)v, 1.f);
    }
}

// ---------------- bucket fill: group src ids by dst ---------------------------
__global__ void k_fill() {
    int e = blockIdx.x * blockDim.x + threadIdx.x;
    if (e >= EDGES) return;
    int d = g_dst[e];
    int p = atomicAdd(&g_cur[d], 1);
    g_esrc[g_off[d] + p] = g_src[e];
}

// ---------------- layer-1 gather: agg1[n] = mean over nbrs of x ---------------
// Two warps per node (128 cols each); lane owns one float4.
__global__ void k_gather1(const float* __restrict__ x) {
    int gw   = (blockIdx.x * blockDim.x + threadIdx.x) >> 5;
    int node = gw >> 1;
    if (node >= NODES) return;
    int half = gw & 1;
    int lane = threadIdx.x & 31;
    int c = half * 128 + lane * 4;

    int e   = g_off[node];
    int end = e + g_cnt[node];
    float4 acc = make_float4(0.f, 0.f, 0.f, 0.f);
    for (; e + 1 < end; e += 2) {
        int s0 = g_esrc[e], s1 = g_esrc[e + 1];
        float4 v0 = *(const float4*)(x + (size_t)s0 * 256 + c);
        float4 v1 = *(const float4*)(x + (size_t)s1 * 256 + c);
        acc.x += v0.x; acc.y += v0.y; acc.z += v0.z; acc.w += v0.w;
        acc.x += v1.x; acc.y += v1.y; acc.z += v1.z; acc.w += v1.w;
    }
    if (e < end) {
        int s0 = g_esrc[e];
        float4 v0 = *(const float4*)(x + (size_t)s0 * 256 + c);
        acc.x += v0.x; acc.y += v0.y; acc.z += v0.z; acc.w += v0.w;
    }
    float inv = g_inv[node];
    acc.x *= inv; acc.y *= inv; acc.z *= inv; acc.w *= inv;
    *(float4*)(g_agg1 + (size_t)node * 256 + c) = acc;
}

// ---------------- GEMM 1: h = relu(agg1@W1l + x@W1r + b1) ----------------------
// BM=BN=128, BK=16, double-buffered smem, 256 threads, 8x8 per thread.
__global__ __launch_bounds__(256, 2) void k_gemm1(const float* __restrict__ x,
                        const float* __restrict__ W1l,
                        const float* __restrict__ b1,
                        const float* __restrict__ W1r) {
    __shared__ float As[2][16][132];
    __shared__ float Bs[2][16][128];
    const int t  = threadIdx.x;
    const int tx = t & 15, ty = t >> 4;
    const int row0 = blockIdx.y * 128, col0 = blockIdx.x * 128;
    const int ar = t >> 2,  ak = (t & 3) << 2;   // A: rows ar, ar+64; k off ak
    const int br = t >> 5,  bc = (t & 31) << 2;  // B: k rows br, br+8; col bc

    float acc[8][8];
#pragma unroll
    for (int i = 0; i < 8; i++)
#pragma unroll
        for (int j = 0; j < 8; j++) acc[i][j] = 0.f;

    float4 pa0, pa1, pb0, pb1;

    auto gload = [&](int tile) {
        int pass = tile >> 4;
        int kk = (tile & 15) << 4;
        const float* A = pass ? x   : g_agg1;
        const float* B = pass ? W1r : W1l;
        int r0 = row0 + ar, r1 = row0 + ar + 64;
        pa0 = (r0 < NODES) ? *(const float4*)(A + (size_t)r0 * 256 + kk + ak)
                           : make_float4(0.f, 0.f, 0.f, 0.f);
        pa1 = (r1 < NODES) ? *(const float4*)(A + (size_t)r1 * 256 + kk + ak)
                           : make_float4(0.f, 0.f, 0.f, 0.f);
        pb0 = *(const float4*)(B + (size_t)(kk + br) * 256 + col0 + bc);
        pb1 = *(const float4*)(B + (size_t)(kk + br + 8) * 256 + col0 + bc);
    };
    auto sts = [&](int buf) {
        As[buf][ak + 0][ar] = pa0.x;
        As[buf][ak + 1][ar] = pa0.y;
        As[buf][ak + 2][ar] = pa0.z;
        As[buf][ak + 3][ar] = pa0.w;
        As[buf][ak + 0][ar + 64] = pa1.x;
        As[buf][ak + 1][ar + 64] = pa1.y;
        As[buf][ak + 2][ar + 64] = pa1.z;
        As[buf][ak + 3][ar + 64] = pa1.w;
        *(float4*)&Bs[buf][br][bc]     = pb0;
        *(float4*)&Bs[buf][br + 8][bc] = pb1;
    };
    auto comp = [&](int buf) {
#pragma unroll
        for (int k = 0; k < 16; k++) {
            float a[8], b[8];
            *(float4*)&a[0] = *(const float4*)&As[buf][k][ty * 8];
            *(float4*)&a[4] = *(const float4*)&As[buf][k][ty * 8 + 4];
            *(float4*)&b[0] = *(const float4*)&Bs[buf][k][tx * 8];
            *(float4*)&b[4] = *(const float4*)&Bs[buf][k][tx * 8 + 4];
#pragma unroll
            for (int i = 0; i < 8; i++)
#pragma unroll
                for (int j = 0; j < 8; j++) acc[i][j] += a[i] * b[j];
        }
    };

    gload(0);
    sts(0);
    __syncthreads();
#pragma unroll 1
    for (int tile = 0; tile < 32; tile++) {
        int buf = tile & 1;
        if (tile + 1 < 32) gload(tile + 1);
        comp(buf);
        if (tile + 1 < 32) sts(buf ^ 1);
        __syncthreads();
    }

#pragma unroll
    for (int i = 0; i < 8; i++) {
        int r = row0 + ty * 8 + i;
        if (r < NODES) {
#pragma unroll
            for (int j = 0; j < 8; j++) {
                int c = col0 + tx * 8 + j;
                g_h[(size_t)r * 256 + c] = fmaxf(acc[i][j] + b1[c], 0.f);
            }
        }
    }
}

// ---------------- GEMM 2: p = h@[W2l | W2r]  (block col chooses the matrix) ---
__global__ __launch_bounds__(256, 2) void k_gemm2(const float* __restrict__ W2l,
                        const float* __restrict__ W2r) {
    __shared__ float As[2][16][132];
    __shared__ float Bs[2][16][128];
    const int t  = threadIdx.x;
    const int tx = t & 15, ty = t >> 4;
    const int row0 = blockIdx.y * 128;
    const int col0 = blockIdx.x * 128;
    const float* B = blockIdx.x ? W2r : W2l;   // each B is [256,128] row-major
    const int ar = t >> 2,  ak = (t & 3) << 2;
    const int br = t >> 5,  bc = (t & 31) << 2;

    float acc[8][8];
#pragma unroll
    for (int i = 0; i < 8; i++)
#pragma unroll
        for (int j = 0; j < 8; j++) acc[i][j] = 0.f;

    float4 pa0, pa1, pb0, pb1;

    auto gload = [&](int tile) {
        int kk = tile << 4;
        int r0 = row0 + ar, r1 = row0 + ar + 64;
        pa0 = (r0 < NODES) ? *(const float4*)(g_h + (size_t)r0 * 256 + kk + ak)
                           : make_float4(0.f, 0.f, 0.f, 0.f);
        pa1 = (r1 < NODES) ? *(const float4*)(g_h + (size_t)r1 * 256 + kk + ak)
                           : make_float4(0.f, 0.f, 0.f, 0.f);
        pb0 = *(const float4*)(B + (size_t)(kk + br) * 128 + bc);
        pb1 = *(const float4*)(B + (size_t)(kk + br + 8) * 128 + bc);
    };
    auto sts = [&](int buf) {
        As[buf][ak + 0][ar] = pa0.x;
        As[buf][ak + 1][ar] = pa0.y;
        As[buf][ak + 2][ar] = pa0.z;
        As[buf][ak + 3][ar] = pa0.w;
        As[buf][ak + 0][ar + 64] = pa1.x;
        As[buf][ak + 1][ar + 64] = pa1.y;
        As[buf][ak + 2][ar + 64] = pa1.z;
        As[buf][ak + 3][ar + 64] = pa1.w;
        *(float4*)&Bs[buf][br][bc]     = pb0;
        *(float4*)&Bs[buf][br + 8][bc] = pb1;
    };
    auto comp = [&](int buf) {
#pragma unroll
        for (int k = 0; k < 16; k++) {
            float a[8], b[8];
            *(float4*)&a[0] = *(const float4*)&As[buf][k][ty * 8];
            *(float4*)&a[4] = *(const float4*)&As[buf][k][ty * 8 + 4];
            *(float4*)&b[0] = *(const float4*)&Bs[buf][k][tx * 8];
            *(float4*)&b[4] = *(const float4*)&Bs[buf][k][tx * 8 + 4];
#pragma unroll
            for (int i = 0; i < 8; i++)
#pragma unroll
                for (int j = 0; j < 8; j++) acc[i][j] += a[i] * b[j];
        }
    };

    gload(0);
    sts(0);
    __syncthreads();
#pragma unroll 1
    for (int tile = 0; tile < 16; tile++) {
        int buf = tile & 1;
        if (tile + 1 < 16) gload(tile + 1);
        comp(buf);
        if (tile + 1 < 16) sts(buf ^ 1);
        __syncthreads();
    }

#pragma unroll
    for (int i = 0; i < 8; i++) {
        int r = row0 + ty * 8 + i;
        if (r < NODES) {
#pragma unroll
            for (int j = 0; j < 8; j++) {
                g_p[(size_t)r * 256 + col0 + tx * 8 + j] = acc[i][j];
            }
        }
    }
}

// ---- layer-2 gather fused with epilogue: out = sigmoid(mean(p_l)+b2+p_r) -----
// One warp per node; lane owns one float4 of the 128 output cols.
__global__ void k_gather2_final(const float* __restrict__ b2,
                                float* __restrict__ out) {
    int node = (blockIdx.x * blockDim.x + threadIdx.x) >> 5;
    if (node >= NODES) return;
    int lane = threadIdx.x & 31;
    int c = lane * 4;

    int e   = g_off[node];
    int end = e + g_cnt[node];
    float4 acc = make_float4(0.f, 0.f, 0.f, 0.f);
    for (; e + 1 < end; e += 2) {
        int s0 = g_esrc[e], s1 = g_esrc[e + 1];
        float4 v0 = *(const float4*)(g_p + (size_t)s0 * 256 + c);
        float4 v1 = *(const float4*)(g_p + (size_t)s1 * 256 + c);
        acc.x += v0.x; acc.y += v0.y; acc.z += v0.z; acc.w += v0.w;
        acc.x += v1.x; acc.y += v1.y; acc.z += v1.z; acc.w += v1.w;
    }
    if (e < end) {
        int s0 = g_esrc[e];
        float4 v0 = *(const float4*)(g_p + (size_t)s0 * 256 + c);
        acc.x += v0.x; acc.y += v0.y; acc.z += v0.z; acc.w += v0.w;
    }
    float inv = g_inv[node];
    float4 bb = *(const float4*)(b2 + c);
    float4 rr = *(const float4*)(g_p + (size_t)node * 256 + 128 + c);
    float4 o;
    o.x = 1.f / (1.f + expf(-(acc.x * inv + bb.x + rr.x)));
    o.y = 1.f / (1.f + expf(-(acc.y * inv + bb.y + rr.y)));
    o.z = 1.f / (1.f + expf(-(acc.z * inv + bb.z + rr.z)));
    o.w = 1.f / (1.f + expf(-(acc.w * inv + bb.w + rr.w)));
    *(float4*)(out + (size_t)node * 128 + c) = o;
}

// ---------------- launch -------------------------------------------------------
extern "C" void kernel_launch(void* const* d_in, const int* in_sizes, int n_in,
                              void* d_out, int out_size) {
    (void)in_sizes; (void)n_in; (void)out_size;
    const float* x   = (const float*)d_in[0];
    const void*  ei  = d_in[1];                 // int64 or int32; decoded on device
    const float* W1l = (const float*)d_in[2];
    const float* b1  = (const float*)d_in[3];
    const float* W1r = (const float*)d_in[4];
    const float* W2l = (const float*)d_in[5];
    const float* b2  = (const float*)d_in[6];
    const float* W2r = (const float*)d_in[7];
    float* out = (float*)d_out;

    k_init<<<(NODES + 255) / 256, 256>>>();
    k_edges<<<(EDGES + 255) / 256, 256>>>(ei);
    k_alloc<<<(NODES + 255) / 256, 256>>>();
    k_fill<<<(EDGES + 255) / 256, 256>>>();
    k_gather1<<<(NODES * 2 * 32 + 255) / 256, 256>>>(x);
    dim3 grid_g(2, (NODES + 127) / 128);
    k_gemm1<<<grid_g, 256>>>(x, W1l, b1, W1r);
    k_gemm2<<<grid_g, 256>>>(W2l, W2r);
    k_gather2_final<<<(NODES * 32 + 255) / 256, 256>>>(b2, out);
}

// round 5
// speedup vs baseline: 3.1302x; 1.5791x over previous
#include <cuda_runtime.h>
#include <cuda_bf16.h>
#include <math.h>
#include <stdint.h>

#define NODES 50000
#define NODES_PAD 50048            // 391 tiles * 128
#define EDGES 800000
#define NTILES 391

// ---------------- scratch (static device globals; no allocs allowed) ----------
// A matrices stored as bf16 triple-interleaved streams:
//   A pattern per original k: [hi, hi, lo]   B pattern: [hi, lo, hi]
//   plain GEMM over K''=3K then yields hi*hi + hi*lo + lo*hi  (3xBF16 split)
__device__ __align__(128) unsigned char g_a1[(size_t)NODES_PAD * 3072]; // [N][1536 bf16]: cols 0..767 agg, 768..1535 x
__device__ __align__(128) unsigned char g_a2[(size_t)NODES_PAD * 1536]; // [N][768 bf16] : h triples
__device__ __align__(128) unsigned char g_b1[256 * 3072];               // [256 n][1536 bf16] from W1l;W1r (transposed)
__device__ __align__(128) unsigned char g_b2[256 * 1536];               // [256 n][768 bf16]  from W2l|W2r (transposed)
__device__ __align__(128) float g_p[(size_t)NODES_PAD * 256];           // cols 0..127: h@W2l, 128..255: h@W2r
__device__ int   g_cnt [NODES];
__device__ float g_inv [NODES];
__device__ int   g_src [EDGES];
__device__ int   g_dst [EDGES];
__device__ int   g_off [NODES];
__device__ int   g_cur [NODES];
__device__ int   g_esrc[EDGES];
__device__ int   g_total;

// ---------------- PTX helpers ---------------------------------------------------
__device__ __forceinline__ uint32_t smem_u32(const void* p) {
    uint32_t a;
    asm("{ .reg .u64 t; cvta.to.shared.u64 t, %1; cvt.u32.u64 %0, t; }" : "=r"(a) : "l"(p));
    return a;
}
#define SW128(o) ((o) ^ (((o) >> 3) & 0x70))

__device__ __forceinline__ void cp16(uint32_t dst, const void* src) {
    asm volatile("cp.async.cg.shared.global [%0], [%1], 16;" :: "r"(dst), "l"(src));
}
#define CP_COMMIT() asm volatile("cp.async.commit_group;" ::: "memory")
#define CP_WAIT(n)  asm volatile("cp.async.wait_group %0;" :: "n"(n) : "memory")

__device__ __forceinline__ void ldsm4(uint32_t addr, uint32_t* r) {
    asm volatile("ldmatrix.sync.aligned.m8n8.x4.shared.b16 {%0,%1,%2,%3}, [%4];"
        : "=r"(r[0]), "=r"(r[1]), "=r"(r[2]), "=r"(r[3]) : "r"(addr));
}
__device__ __forceinline__ void mma16816(float* c, const uint32_t* a, uint32_t b0, uint32_t b1) {
    asm volatile("mma.sync.aligned.m16n8k16.row.col.f32.bf16.bf16.f32 "
        "{%0,%1,%2,%3}, {%4,%5,%6,%7}, {%8,%9}, {%0,%1,%2,%3};"
        : "+f"(c[0]), "+f"(c[1]), "+f"(c[2]), "+f"(c[3])
        : "r"(a[0]), "r"(a[1]), "r"(a[2]), "r"(a[3]), "r"(b0), "r"(b1));
}

// bf16 split helpers
__device__ __forceinline__ unsigned short f2bf(float v) {
    __nv_bfloat16 h = __float2bfloat16_rn(v);
    return *reinterpret_cast<unsigned short*>(&h);
}
__device__ __forceinline__ float bf2f(unsigned short u) {
    __nv_bfloat16 h = *reinterpret_cast<__nv_bfloat16*>(&u);
    return __bfloat162float(h);
}
__device__ __forceinline__ void bsplit(float v, unsigned short& hi, unsigned short& lo) {
    hi = f2bf(v);
    lo = f2bf(v - bf2f(hi));
}

// ---------------- init ----------------------------------------------------------
__global__ void k_init() {
    int i = blockIdx.x * blockDim.x + threadIdx.x;
    if (i < NODES) { g_cnt[i] = 0; g_cur[i] = 0; }
    if (i == 0) g_total = 0;
}

// ---------------- edge decode + degree count ------------------------------------
__global__ void k_edges(const void* __restrict__ ei_raw) {
    int e = blockIdx.x * blockDim.x + threadIdx.x;
    if (e >= EDGES) return;
    const int* w = (const int*)ei_raw;
    bool is64 = ((w[1] | w[3] | w[5] | w[7] | w[9] | w[11] | w[13] | w[15]) == 0);
    int s, d;
    if (is64) {
        const long long* e64 = (const long long*)ei_raw;
        s = (int)e64[e];
        d = (int)e64[EDGES + e];
    } else {
        s = w[e];
        d = w[EDGES + e];
    }
    g_src[e] = s;
    g_dst[e] = d;
    atomicAdd(&g_cnt[d], 1);
}

// ------- bucket allocation: per-block scan + one global atomic; also 1/deg -----
__global__ void k_alloc() {
    __shared__ int s[256];
    __shared__ int base;
    int t = threadIdx.x;
    int i = blockIdx.x * 256 + t;
    int v = (i < NODES) ? g_cnt[i] : 0;
    s[t] = v;
    __syncthreads();
#pragma unroll
    for (int d = 1; d < 256; d <<= 1) {
        int add = (t >= d) ? s[t - d] : 0;
        __syncthreads();
        s[t] += add;
        __syncthreads();
    }
    int incl = s[t];
    if (t == 255) base = atomicAdd(&g_total, incl);
    __syncthreads();
    if (i < NODES) {
        g_off[i] = base + incl - v;
        g_inv[i] = 1.f / fmaxf((float)v, 1.f);
    }
}

__global__ void k_fill() {
    int e = blockIdx.x * blockDim.x + threadIdx.x;
    if (e >= EDGES) return;
    int d = g_dst[e];
    int p = atomicAdd(&g_cur[d], 1);
    g_esrc[g_off[d] + p] = g_src[e];
}

// ------------- x -> bf16 triples into g_a1 cols [768..1536) ---------------------
__global__ void k_convx(const float* __restrict__ x) {
    int id = blockIdx.x * blockDim.x + threadIdx.x;
    if (id >= NODES * 64) return;
    int node = id >> 6;
    int j = id & 63;
    float4 v = *(const float4*)(x + (size_t)node * 256 + j * 4);
    unsigned short h0, l0, h1, l1, h2, l2, h3, l3;
    bsplit(v.x, h0, l0); bsplit(v.y, h1, l1);
    bsplit(v.z, h2, l2); bsplit(v.w, h3, l3);
    uint2* dst = (uint2*)(g_a1 + (size_t)node * 3072 + 1536 + j * 24);
    dst[0] = make_uint2((uint32_t)h0 | ((uint32_t)h0 << 16), (uint32_t)l0 | ((uint32_t)h1 << 16));
    dst[1] = make_uint2((uint32_t)h1 | ((uint32_t)l1 << 16), (uint32_t)h2 | ((uint32_t)h2 << 16));
    dst[2] = make_uint2((uint32_t)l2 | ((uint32_t)h3 << 16), (uint32_t)h3 | ((uint32_t)l3 << 16));
}

// ------------- weights -> transposed bf16 triples ([hi,lo,hi] pattern) ----------
__global__ void k_wprep(const float* __restrict__ W1l, const float* __restrict__ W1r,
                        const float* __restrict__ W2l, const float* __restrict__ W2r) {
    int id = blockIdx.x * blockDim.x + threadIdx.x;
    if (id < 256 * 512) {
        int n = id >> 9, k = id & 511;
        float w = (k < 256) ? W1l[k * 256 + n] : W1r[(k - 256) * 256 + n];
        unsigned short hi, lo;
        bsplit(w, hi, lo);
        unsigned short* d = (unsigned short*)(g_b1 + (size_t)n * 3072 + 6 * k);
        d[0] = hi; d[1] = lo; d[2] = hi;
    } else if (id < 256 * 512 + 256 * 256) {
        int id2 = id - 256 * 512;
        int n = id2 >> 8, k = id2 & 255;
        float w = (n < 128) ? W2l[k * 128 + n] : W2r[k * 128 + (n - 128)];
        unsigned short hi, lo;
        bsplit(w, hi, lo);
        unsigned short* d = (unsigned short*)(g_b2 + (size_t)n * 1536 + 6 * k);
        d[0] = hi; d[1] = lo; d[2] = hi;
    }
}

// ------------- layer-1 gather -> bf16 triples into g_a1 cols [0..768) -----------
__global__ void k_gather1(const float* __restrict__ x) {
    int gw   = (blockIdx.x * blockDim.x + threadIdx.x) >> 5;
    int node = gw >> 1;
    if (node >= NODES) return;
    int half = gw & 1;
    int lane = threadIdx.x & 31;
    int c = half * 128 + lane * 4;

    int e   = g_off[node];
    int end = e + g_cnt[node];
    float4 acc = make_float4(0.f, 0.f, 0.f, 0.f);
    for (; e + 1 < end; e += 2) {
        int s0 = g_esrc[e], s1 = g_esrc[e + 1];
        float4 v0 = *(const float4*)(x + (size_t)s0 * 256 + c);
        float4 v1 = *(const float4*)(x + (size_t)s1 * 256 + c);
        acc.x += v0.x; acc.y += v0.y; acc.z += v0.z; acc.w += v0.w;
        acc.x += v1.x; acc.y += v1.y; acc.z += v1.z; acc.w += v1.w;
    }
    if (e < end) {
        int s0 = g_esrc[e];
        float4 v0 = *(const float4*)(x + (size_t)s0 * 256 + c);
        acc.x += v0.x; acc.y += v0.y; acc.z += v0.z; acc.w += v0.w;
    }
    float inv = g_inv[node];
    acc.x *= inv; acc.y *= inv; acc.z *= inv; acc.w *= inv;
    unsigned short h0, l0, h1, l1, h2, l2, h3, l3;
    bsplit(acc.x, h0, l0); bsplit(acc.y, h1, l1);
    bsplit(acc.z, h2, l2); bsplit(acc.w, h3, l3);
    uint2* dst = (uint2*)(g_a1 + (size_t)node * 3072 + half * 768 + lane * 24);
    dst[0] = make_uint2((uint32_t)h0 | ((uint32_t)h0 << 16), (uint32_t)l0 | ((uint32_t)h1 << 16));
    dst[1] = make_uint2((uint32_t)h1 | ((uint32_t)l1 << 16), (uint32_t)h2 | ((uint32_t)h2 << 16));
    dst[2] = make_uint2((uint32_t)l2 | ((uint32_t)h3 << 16), (uint32_t)h3 | ((uint32_t)l3 << 16));
}

// ---------------- warp-MMA bf16 GEMM: D[128 rows, 128 cols] per CTA -------------
// MODE 1: A=g_a1 (K''=1536, 24 tiles), B=g_b1; epilogue bias+relu+split -> g_a2
// MODE 2: A=g_a2 (K''=768, 12 tiles),  B=g_b2; epilogue raw fp32 -> g_p
// 3-stage cp.async pipeline; SW128 smem; ldmatrix fragments; mma.m16n8k16.
#define STAGE_BYTES 32768                 // A 16KB + B 16KB
#define SMEM_DYN (3 * STAGE_BYTES)

template <int MODE>
__global__ __launch_bounds__(256, 2) void k_gemm(const float* __restrict__ bias) {
    constexpr int RB = (MODE == 1) ? 3072 : 1536;   // stream row bytes
    constexpr int KT = (MODE == 1) ? 24 : 12;       // 128-byte k-tiles (64 bf16)
    const unsigned char* gA = (MODE == 1) ? g_a1 : g_a2;
    const unsigned char* gB = (MODE == 1) ? g_b1 : g_b2;

    extern __shared__ __align__(128) unsigned char dsm[];
    const int t      = threadIdx.x;
    const int lane   = t & 31;
    const int wid    = t >> 5;
    const int warp_m = wid & 3;       // 4 M-groups of 32 rows
    const int warp_n = wid >> 2;      // 2 N-groups of 64 cols
    const int row0   = blockIdx.x * 128;
    const int col0   = blockIdx.y * 128;
    const uint32_t base = smem_u32(dsm);

    float c[2][8][4];
#pragma unroll
    for (int i = 0; i < 2; i++)
#pragma unroll
        for (int j = 0; j < 8; j++)
#pragma unroll
            for (int q = 0; q < 4; q++) c[i][j][q] = 0.f;

    // per-thread load slots: row r (0..127), 4 chunks of 16B at ch0
    const int lrow = t >> 1;
    const int ch0  = (t & 1) * 4;

    auto load_tile = [&](int kt, int s) {
        uint32_t sa = base + s * STAGE_BYTES;
        uint32_t sb = sa + 16384;
        const unsigned char* srcA = gA + (size_t)(row0 + lrow) * RB + (size_t)kt * 128 + ch0 * 16;
#pragma unroll
        for (int i = 0; i < 4; i++)
            cp16(sa + SW128(lrow * 128 + (ch0 + i) * 16), srcA + i * 16);
        const unsigned char* srcB = gB + (size_t)(col0 + lrow) * RB + (size_t)kt * 128 + ch0 * 16;
#pragma unroll
        for (int i = 0; i < 4; i++)
            cp16(sb + SW128(lrow * 128 + (ch0 + i) * 16), srcB + i * 16);
        CP_COMMIT();
    };

    const int lj = lane >> 3;     // 0..3 (ldmatrix sub-matrix)
    const int lr = lane & 7;

    auto compute = [&](int s) {
        uint32_t sa = base + s * STAGE_BYTES;
        uint32_t sb = sa + 16384;
#pragma unroll
        for (int ks = 0; ks < 4; ks++) {
            int cb = ks * 32 + (lj >> 1) * 16;
            uint32_t af[2][4];
#pragma unroll
            for (int mm = 0; mm < 2; mm++) {
                int row = warp_m * 32 + mm * 16 + (lj & 1) * 8 + lr;
                ldsm4(sa + SW128(row * 128 + cb), af[mm]);
            }
            uint32_t bf[4][4];
#pragma unroll
            for (int np = 0; np < 4; np++) {
                int row = warp_n * 64 + np * 16 + (lj & 1) * 8 + lr;
                ldsm4(sb + SW128(row * 128 + cb), bf[np]);
            }
#pragma unroll
            for (int mm = 0; mm < 2; mm++)
#pragma unroll
                for (int nn = 0; nn < 8; nn++)
                    mma16816(c[mm][nn], af[mm], bf[nn >> 1][nn & 1], bf[nn >> 1][(nn & 1) + 2]);
        }
    };

    load_tile(0, 0);
    load_tile(1, 1);
#pragma unroll 1
    for (int kt = 0; kt < KT; kt++) {
        CP_WAIT(1);
        __syncthreads();
        if (kt + 2 < KT) load_tile(kt + 2, (kt + 2) % 3);
        compute(kt % 3);
    }

    // ---------------- epilogue -------------------------------------------------
    const int qr = lane >> 2;
    const int qc = (lane & 3) * 2;
#pragma unroll
    for (int mm = 0; mm < 2; mm++) {
#pragma unroll
        for (int nn = 0; nn < 8; nn++) {
            int col = col0 + warp_n * 64 + nn * 8 + qc;
#pragma unroll
            for (int h = 0; h < 2; h++) {
                int row = row0 + warp_m * 32 + mm * 16 + qr + h * 8;
                float v0 = c[mm][nn][2 * h + 0];
                float v1 = c[mm][nn][2 * h + 1];
                if (MODE == 1) {
                    v0 = fmaxf(v0 + __ldg(&bias[col]), 0.f);
                    v1 = fmaxf(v1 + __ldg(&bias[col + 1]), 0.f);
                    unsigned short h0, l0, h1, l1;
                    bsplit(v0, h0, l0);
                    bsplit(v1, h1, l1);
                    uint32_t* d = (uint32_t*)(g_a2 + (size_t)row * 1536 + 6 * col);
                    d[0] = (uint32_t)h0 | ((uint32_t)h0 << 16);
                    d[1] = (uint32_t)l0 | ((uint32_t)h1 << 16);
                    d[2] = (uint32_t)h1 | ((uint32_t)l1 << 16);
                } else {
                    *(float2*)(g_p + (size_t)row * 256 + col) = make_float2(v0, v1);
                }
            }
        }
    }
}

// ---- layer-2 gather fused with epilogue: out = sigmoid(mean(p_l)+b2+p_r) ------
__global__ void k_gather2_final(const float* __restrict__ b2,
                                float* __restrict__ out) {
    int node = (blockIdx.x * blockDim.x + threadIdx.x) >> 5;
    if (node >= NODES) return;
    int lane = threadIdx.x & 31;
    int c = lane * 4;

    int e   = g_off[node];
    int end = e + g_cnt[node];
    float4 acc = make_float4(0.f, 0.f, 0.f, 0.f);
    for (; e + 1 < end; e += 2) {
        int s0 = g_esrc[e], s1 = g_esrc[e + 1];
        float4 v0 = *(const float4*)(g_p + (size_t)s0 * 256 + c);
        float4 v1 = *(const float4*)(g_p + (size_t)s1 * 256 + c);
        acc.x += v0.x; acc.y += v0.y; acc.z += v0.z; acc.w += v0.w;
        acc.x += v1.x; acc.y += v1.y; acc.z += v1.z; acc.w += v1.w;
    }
    if (e < end) {
        int s0 = g_esrc[e];
        float4 v0 = *(const float4*)(g_p + (size_t)s0 * 256 + c);
        acc.x += v0.x; acc.y += v0.y; acc.z += v0.z; acc.w += v0.w;
    }
    float inv = g_inv[node];
    float4 bb = *(const float4*)(b2 + c);
    float4 rr = *(const float4*)(g_p + (size_t)node * 256 + 128 + c);
    float4 o;
    o.x = 1.f / (1.f + expf(-(acc.x * inv + bb.x + rr.x)));
    o.y = 1.f / (1.f + expf(-(acc.y * inv + bb.y + rr.y)));
    o.z = 1.f / (1.f + expf(-(acc.z * inv + bb.z + rr.z)));
    o.w = 1.f / (1.f + expf(-(acc.w * inv + bb.w + rr.w)));
    *(float4*)(out + (size_t)node * 128 + c) = o;
}

// ---------------- launch --------------------------------------------------------
extern "C" void kernel_launch(void* const* d_in, const int* in_sizes, int n_in,
                              void* d_out, int out_size) {
    (void)in_sizes; (void)n_in; (void)out_size;
    const float* x   = (const float*)d_in[0];
    const void*  ei  = d_in[1];
    const float* W1l = (const float*)d_in[2];
    const float* b1  = (const float*)d_in[3];
    const float* W1r = (const float*)d_in[4];
    const float* W2l = (const float*)d_in[5];
    const float* b2  = (const float*)d_in[6];
    const float* W2r = (const float*)d_in[7];
    float* out = (float*)d_out;

    cudaFuncSetAttribute(k_gemm<1>, cudaFuncAttributeMaxDynamicSharedMemorySize, SMEM_DYN);
    cudaFuncSetAttribute(k_gemm<2>, cudaFuncAttributeMaxDynamicSharedMemorySize, SMEM_DYN);

    k_init<<<(NODES + 255) / 256, 256>>>();
    k_edges<<<(EDGES + 255) / 256, 256>>>(ei);
    k_alloc<<<(NODES + 255) / 256, 256>>>();
    k_fill<<<(EDGES + 255) / 256, 256>>>();
    k_wprep<<<(256 * 512 + 256 * 256 + 255) / 256, 256>>>(W1l, W1r, W2l, W2r);
    k_convx<<<(NODES * 64 + 255) / 256, 256>>>(x);
    k_gather1<<<(NODES * 2 * 32 + 255) / 256, 256>>>(x);
    dim3 grid_g(NTILES, 2);
    k_gemm<1><<<grid_g, 256, SMEM_DYN>>>(b1);
    k_gemm<2><<<grid_g, 256, SMEM_DYN>>>(b1 /*unused*/);
    k_gather2_final<<<(NODES * 32 + 255) / 256, 256>>>(b2, out);
}